// round 9
// baseline (speedup 1.0000x reference)
#include <cuda_runtime.h>
#include <cstdint>

#define DIMX 1024
#define NEXP 8
#define HIDX 4096
#define TTOK 4096   // B*S = 2*2048

// ---------------- static scratch (no allocations allowed) ----------------
__device__ signed char g_wq1[(size_t)NEXP * HIDX * DIMX];   // ternary w1
__device__ signed char g_wq2[(size_t)NEXP * DIMX * HIDX];   // ternary w2
__device__ signed char g_wqr[NEXP * DIMX];
__device__ signed char g_wqn[NEXP * DIMX];
__device__ float g_partial[18 * 64];
__device__ float g_mval[18];
__device__ signed char g_xq[(size_t)TTOK * DIMX];
__device__ float g_deqx[TTOK];
__device__ int   g_cnt[NEXP];
__device__ int   g_tok[NEXP * TTOK];
__device__ int   g_tpe[TTOK * 2];    // (expert<<16)|pos per token slot
__device__ float g_tg[TTOK * 2];     // gates per token slot
__device__ float g_h[(size_t)2 * TTOK * HIDX];               // fp32 hidden
__device__ signed char g_hq[(size_t)2 * TTOK * HIDX];        // int8 hidden
__device__ float g_deqh[2 * TTOK];
__device__ float g_y[(size_t)2 * TTOK * DIMX];               // ungated expert outputs

// ---------------- helpers ----------------
__device__ __forceinline__ signed char terq(float x) {
    float r = rintf(x);
    r = fminf(1.f, fmaxf(-1.f, r));
    return (signed char)(int)r;
}
__device__ __forceinline__ signed char qi8(float x) {
    float r = rintf(x);
    r = fminf(127.f, fmaxf(-128.f, r));
    return (signed char)(int)r;
}
__device__ __forceinline__ uint32_t s2u(const void* p) {
    uint32_t a;
    asm("{ .reg .u64 t; cvta.to.shared.u64 t, %1; cvt.u32.u64 %0, t; }" : "=r"(a) : "l"(p));
    return a;
}
__device__ __forceinline__ void ldsm4(unsigned& r0, unsigned& r1, unsigned& r2, unsigned& r3,
                                      uint32_t a) {
    asm volatile("ldmatrix.sync.aligned.m8n8.x4.shared.b16 {%0,%1,%2,%3}, [%4];"
                 : "=r"(r0), "=r"(r1), "=r"(r2), "=r"(r3) : "r"(a));
}

// ---------------- 1) weight stats: per-tensor sum |w| ----------------
__global__ void stats_partial(const float* __restrict__ wr, const float* __restrict__ wn,
                              const float* __restrict__ w1, const float* __restrict__ w2) {
    int slot = blockIdx.y, chunk = blockIdx.x;
    const float4* p;
    int nvec;
    if (slot < 2) {
        if (chunk != 0) return;
        p = (const float4*)(slot ? wn : wr);
        nvec = NEXP * DIMX / 4;
    } else if (slot < 10) {
        p = (const float4*)(w1 + (size_t)(slot - 2) * HIDX * DIMX) + (size_t)chunk * 16384;
        nvec = 16384;
    } else {
        p = (const float4*)(w2 + (size_t)(slot - 10) * DIMX * HIDX) + (size_t)chunk * 16384;
        nvec = 16384;
    }
    float s = 0.f;
    for (int i = threadIdx.x; i < nvec; i += 256) {
        float4 v = p[i];
        s += fabsf(v.x) + fabsf(v.y) + fabsf(v.z) + fabsf(v.w);
    }
    __shared__ float sh[8];
    #pragma unroll
    for (int o = 16; o; o >>= 1) s += __shfl_xor_sync(0xffffffffu, s, o);
    if ((threadIdx.x & 31) == 0) sh[threadIdx.x >> 5] = s;
    __syncthreads();
    if (threadIdx.x == 0) {
        float t = 0.f;
        #pragma unroll
        for (int j = 0; j < 8; j++) t += sh[j];
        g_partial[slot * 64 + chunk] = t;
    }
}

// ---------------- 2) finalize: mvals + small-weight ternarize + zero counts ----------------
__global__ void finalize(const float* __restrict__ wr, const float* __restrict__ wn) {
    int tid = threadIdx.x;
    __shared__ float sm[18];
    if (tid < 18) {
        int nc = (tid < 2) ? 1 : 64;
        float sum = 0.f;
        for (int c = 0; c < nc; c++) sum += g_partial[tid * 64 + c];
        float nelem = (tid < 2) ? (float)(NEXP * DIMX) : (float)((size_t)HIDX * DIMX);
        float m = fmaxf(sum / nelem, 1e-5f);
        g_mval[tid] = m;
        sm[tid] = m;
    }
    if (tid < NEXP) g_cnt[tid] = 0;
    __syncthreads();
    float sc0 = 1.0f / sm[0], sc1 = 1.0f / sm[1];
    for (int i = tid; i < NEXP * DIMX; i += 256) {
        g_wqr[i] = terq(wr[i] * sc0);
        g_wqn[i] = terq(wn[i] * sc1);
    }
}

// ---------------- 3) mega: big-weight ternarize (z=0,1) + act-quant+router (z=2) ----------------
__global__ __launch_bounds__(256) void mega(const float* __restrict__ w1,
                                            const float* __restrict__ w2,
                                            const float* __restrict__ x,
                                            const float* __restrict__ eps) {
    int z = blockIdx.z;
    int tid = threadIdx.x;
    if (z < 2) {
        size_t i = (size_t)blockIdx.x * 256 + tid;   // float4 index, exactly covers grid
        int e = (int)(i >> 20);
        float sc = 1.0f / g_mval[(z == 0 ? 2 : 10) + e];
        float4 v = ((const float4*)(z == 0 ? w1 : w2))[i];
        char4 c;
        c.x = terq(v.x * sc); c.y = terq(v.y * sc); c.z = terq(v.z * sc); c.w = terq(v.w * sc);
        ((char4*)(z == 0 ? g_wq1 : g_wq2))[i] = c;
        return;
    }
    int t = blockIdx.x;
    if (t >= TTOK) return;

    __shared__ float shs[8], shm[8], svals[8], sdq[1];
    __shared__ int sx[256];

    float4 v = ((const float4*)(x + (size_t)t * DIMX))[tid];
    float ss = v.x * v.x + v.y * v.y + v.z * v.z + v.w * v.w;
    float am = fmaxf(fmaxf(fabsf(v.x), fabsf(v.y)), fmaxf(fabsf(v.z), fabsf(v.w)));
    #pragma unroll
    for (int o = 16; o; o >>= 1) {
        ss += __shfl_xor_sync(0xffffffffu, ss, o);
        am = fmaxf(am, __shfl_xor_sync(0xffffffffu, am, o));
    }
    if ((tid & 31) == 0) { shs[tid >> 5] = ss; shm[tid >> 5] = am; }
    __syncthreads();
    float tss = 0.f, tam = 0.f;
    #pragma unroll
    for (int j = 0; j < 8; j++) { tss += shs[j]; tam = fmaxf(tam, shm[j]); }
    float rs = rsqrtf(tss / (float)DIMX + 1e-6f);
    float a = fmaxf(tam * rs, 1e-5f);
    float sc = 127.0f / a;
    if (tid == 0) { g_deqx[t] = a / 127.0f; sdq[0] = a / 127.0f; }
    char4 c;
    c.x = qi8(v.x * rs * sc); c.y = qi8(v.y * rs * sc);
    c.z = qi8(v.z * rs * sc); c.w = qi8(v.w * rs * sc);
    ((char4*)(g_xq + (size_t)t * DIMX))[tid] = c;
    int ci;
    memcpy(&ci, &c, 4);
    sx[tid] = ci;
    __syncthreads();

    // router: warp w handles expert w
    int w = tid >> 5, lane = tid & 31;
    const int* wrp = (const int*)(g_wqr + w * DIMX);
    const int* wnp = (const int*)(g_wqn + w * DIMX);
    int ar = 0, an = 0;
    #pragma unroll
    for (int j = 0; j < 8; j++) {
        int xi = sx[lane + 32 * j];
        ar = __dp4a(xi, wrp[lane + 32 * j], ar);
        an = __dp4a(xi, wnp[lane + 32 * j], an);
    }
    #pragma unroll
    for (int o = 16; o; o >>= 1) {
        ar += __shfl_xor_sync(0xffffffffu, ar, o);
        an += __shfl_xor_sync(0xffffffffu, an, o);
    }
    if (lane == 0) {
        float dq = sdq[0];
        float lg = (float)ar * dq * g_mval[0];
        float nl = (float)an * dq * g_mval[1];
        float sp = fmaxf(nl, 0.f) + log1pf(expf(-fabsf(nl)));
        svals[w] = lg + eps[t * NEXP + w] * sp;
    }
    __syncthreads();
    if (tid == 0) {
        float v0 = -1e30f, v1 = -1e30f;
        int i0 = 0, i1 = 0;
        #pragma unroll
        for (int e = 0; e < NEXP; e++) {
            float vv = svals[e];
            if (vv > v0) { v1 = v0; i1 = i0; v0 = vv; i0 = e; }
            else if (vv > v1) { v1 = vv; i1 = e; }
        }
        float ex = expf(v1 - v0);
        float inv = 1.0f / (1.0f + ex);
        int p0 = atomicAdd(&g_cnt[i0], 1);
        g_tok[i0 * TTOK + p0] = t;
        int p1 = atomicAdd(&g_cnt[i1], 1);
        g_tok[i1 * TTOK + p1] = t;
        g_tpe[t * 2]     = (i0 << 16) | p0;
        g_tpe[t * 2 + 1] = (i1 << 16) | p1;
        g_tg[t * 2]      = inv;
        g_tg[t * 2 + 1]  = ex * inv;
    }
}

// ---------------- 4/6) pipelined int8 tensor-core grouped GEMM ----------------
// Tile 128x128, BKK=128, 3-stage cp.async pipeline, two barriers per K-iter
// (wait_group is per-thread: the barrier AFTER the wait makes all threads'
// stage-i copies visible; the barrier after compute protects stage reuse).
#define BM 128
#define BN 128
#define BKK 128
#define LDSS 144         // 128 + 16 pad: conflict-free (bank stride 36 == 4 mod 32)
#define STG_STRIDE (2 * BM * LDSS)   // A stage + B stage = 36864
#define GSMEM (3 * STG_STRIDE)       // 3 stages = 110592 B

__device__ __forceinline__ void mma8(int (&c)[4], const unsigned (&a)[4], const unsigned (&b)[2]) {
    asm volatile(
        "mma.sync.aligned.m16n8k32.row.col.s32.s8.s8.s32 "
        "{%0,%1,%2,%3}, {%4,%5,%6,%7}, {%8,%9}, {%0,%1,%2,%3};\n"
        : "+r"(c[0]), "+r"(c[1]), "+r"(c[2]), "+r"(c[3])
        : "r"(a[0]), "r"(a[1]), "r"(a[2]), "r"(a[3]), "r"(b[0]), "r"(b[1]));
}

template <int MODE>
__global__ __launch_bounds__(256) void bit_gemm() {
    constexpr int K = (MODE == 1) ? DIMX : HIDX;
    constexpr int N = (MODE == 1) ? HIDX : DIMX;
    constexpr int NITER = K / BKK;
    const int e = blockIdx.z;
    const int cnt = g_cnt[e];
    const int m0 = blockIdx.y * BM;
    if (m0 >= cnt) return;
    const int n0 = blockIdx.x * BN;
    int off = 0;
    #pragma unroll
    for (int j = 0; j < NEXP; j++) if (j < e) off += g_cnt[j];

    extern __shared__ char dsm[];
    const uint32_t smb = s2u(dsm);

    const int tid = threadIdx.x;
    const int lane = tid & 31, warp = tid >> 5;
    const int wm = warp >> 2, wn = warp & 3;   // 2x4 warp grid, warp tile 64x32

    int acc[4][4][4];
    #pragma unroll
    for (int a = 0; a < 4; a++)
        #pragma unroll
        for (int b = 0; b < 4; b++)
            #pragma unroll
            for (int c = 0; c < 4; c++) acc[a][b][c] = 0;

    const int lr = tid >> 1;            // staged row (0..127)
    const int lcb = (tid & 1) * 64;     // byte offset within 128B k-chunk
    const bool aok = (m0 + lr) < cnt;
    const signed char* Ap;
    if (MODE == 1) {
        int tok = aok ? g_tok[e * TTOK + m0 + lr] : 0;
        Ap = g_xq + (size_t)tok * K + lcb;
    } else {
        int r = aok ? (off + m0 + lr) : 0;
        Ap = g_hq + (size_t)r * K + lcb;
    }
    const unsigned aSz = aok ? 16u : 0u;
    const signed char* wsrc = (MODE == 1) ? g_wq1 : g_wq2;
    const signed char* Bp = wsrc + (size_t)e * N * K + (size_t)(n0 + lr) * K + lcb;

    const uint32_t cpOff = (uint32_t)(lr * LDSS + lcb);
    // ldmatrix lane offsets
    const uint32_t aLO = (uint32_t)((lane & 15) * LDSS + (lane >> 4) * 16);
    const uint32_t bLO = (uint32_t)(((lane >> 4) * 8 + (lane & 7)) * LDSS + ((lane >> 3) & 1) * 16);

    auto prefetch = [&](int it) {
        int s;
        { int m = it; s = m - (m / 3) * 3; }
        uint32_t ab = smb + s * STG_STRIDE + cpOff;
        uint32_t bb = ab + BM * LDSS;
        const signed char* as = Ap;
        const signed char* bs = Bp;
        unsigned asz = 0, bsz = 0;
        if (it < NITER) {
            as = Ap + it * BKK;
            bs = Bp + it * BKK;
            asz = aSz;
            bsz = 16;
        }
        #pragma unroll
        for (int j = 0; j < 4; j++) {
            asm volatile("cp.async.cg.shared.global [%0], [%1], 16, %2;"
                         :: "r"(ab + j * 16), "l"(as + j * 16), "r"(asz) : "memory");
        }
        #pragma unroll
        for (int j = 0; j < 4; j++) {
            asm volatile("cp.async.cg.shared.global [%0], [%1], 16, %2;"
                         :: "r"(bb + j * 16), "l"(bs + j * 16), "r"(bsz) : "memory");
        }
        asm volatile("cp.async.commit_group;" ::: "memory");
    };

    prefetch(0);
    prefetch(1);
    #pragma unroll 1
    for (int i = 0; i < NITER; i++) {
        // stage (i+2)%3 == (i-1)%3 was released by the trailing barrier of iter i-1
        prefetch(i + 2);
        asm volatile("cp.async.wait_group 2;" ::: "memory");   // my group-i copies landed
        __syncthreads();                                       // everyone's group-i copies landed
        int s;
        { int m = i; s = m - (m / 3) * 3; }
        const uint32_t aB = smb + s * STG_STRIDE;
        const uint32_t bB = aB + BM * LDSS;
        #pragma unroll
        for (int ks = 0; ks < 4; ks++) {
            unsigned af[4][4];
            #pragma unroll
            for (int mi = 0; mi < 4; mi++)
                ldsm4(af[mi][0], af[mi][1], af[mi][2], af[mi][3],
                      aB + (uint32_t)((wm * 64 + mi * 16) * LDSS + ks * 32) + aLO);
            unsigned bf[4][2];
            #pragma unroll
            for (int np = 0; np < 2; np++)
                ldsm4(bf[np * 2][0], bf[np * 2][1], bf[np * 2 + 1][0], bf[np * 2 + 1][1],
                      bB + (uint32_t)((wn * 32 + np * 16) * LDSS + ks * 32) + bLO);
            #pragma unroll
            for (int mi = 0; mi < 4; mi++)
                #pragma unroll
                for (int ni = 0; ni < 4; ni++) mma8(acc[mi][ni], af[mi], bf[ni]);
        }
        __syncthreads();                                       // release stage i for reuse
    }

    if (MODE == 1) {
        const float m1 = g_mval[2 + e];
        #pragma unroll
        for (int mi = 0; mi < 4; mi++) {
            #pragma unroll
            for (int half = 0; half < 2; half++) {
                int rrow = wm * 64 + mi * 16 + (lane >> 2) + half * 8;
                int pos = m0 + rrow;
                if (pos < cnt) {
                    float d = g_deqx[g_tok[e * TTOK + pos]] * m1;
                    float* hrow = g_h + (size_t)(off + pos) * HIDX + n0;
                    #pragma unroll
                    for (int ni = 0; ni < 4; ni++) {
                        int col = wn * 32 + ni * 8 + (lane & 3) * 2;
                        float2 v;
                        v.x = fmaxf(0.f, (float)acc[mi][ni][half * 2 + 0] * d);
                        v.y = fmaxf(0.f, (float)acc[mi][ni][half * 2 + 1] * d);
                        *(float2*)(hrow + col) = v;
                    }
                }
            }
        }
    } else {
        const float m2 = g_mval[10 + e];
        #pragma unroll
        for (int mi = 0; mi < 4; mi++) {
            #pragma unroll
            for (int half = 0; half < 2; half++) {
                int rrow = wm * 64 + mi * 16 + (lane >> 2) + half * 8;
                int pos = m0 + rrow;
                if (pos < cnt) {
                    float d = g_deqh[off + pos] * m2;
                    float* yrow = g_y + (size_t)(off + pos) * DIMX + n0;
                    #pragma unroll
                    for (int ni = 0; ni < 4; ni++) {
                        int col = wn * 32 + ni * 8 + (lane & 3) * 2;
                        float2 v;
                        v.x = (float)acc[mi][ni][half * 2 + 0] * d;
                        v.y = (float)acc[mi][ni][half * 2 + 1] * d;
                        *(float2*)(yrow + col) = v;
                    }
                }
            }
        }
    }
}

// ---------------- 5) hidden quant: one block per packed row ----------------
__global__ void h_quant() {
    size_t row = blockIdx.x;   // 0 .. 2*TTOK-1 (all slots always filled)
    const float4* hp = (const float4*)(g_h + row * HIDX);
    int tid = threadIdx.x;
    float4 r[4];
    float ss = 0.f, am = 0.f;
    #pragma unroll
    for (int j = 0; j < 4; j++) {
        r[j] = hp[tid + 256 * j];
        ss += r[j].x * r[j].x + r[j].y * r[j].y + r[j].z * r[j].z + r[j].w * r[j].w;
        am = fmaxf(am, fmaxf(fmaxf(fabsf(r[j].x), fabsf(r[j].y)), fmaxf(fabsf(r[j].z), fabsf(r[j].w))));
    }
    __shared__ float shs[8], shm[8];
    #pragma unroll
    for (int o = 16; o; o >>= 1) {
        ss += __shfl_xor_sync(0xffffffffu, ss, o);
        am = fmaxf(am, __shfl_xor_sync(0xffffffffu, am, o));
    }
    if ((tid & 31) == 0) { shs[tid >> 5] = ss; shm[tid >> 5] = am; }
    __syncthreads();
    float tss = 0.f, tam = 0.f;
    #pragma unroll
    for (int j = 0; j < 8; j++) { tss += shs[j]; tam = fmaxf(tam, shm[j]); }
    float rs = rsqrtf(tss / (float)HIDX + 1e-6f);
    float a = fmaxf(tam * rs, 1e-5f);
    float sc = 127.0f / a;
    if (tid == 0) g_deqh[row] = a / 127.0f;
    char4* dst = (char4*)(g_hq + row * HIDX);
    #pragma unroll
    for (int j = 0; j < 4; j++) {
        char4 c;
        c.x = qi8(r[j].x * rs * sc); c.y = qi8(r[j].y * rs * sc);
        c.z = qi8(r[j].z * rs * sc); c.w = qi8(r[j].w * rs * sc);
        dst[tid + 256 * j] = c;
    }
}

// ---------------- 7) gated combine (deterministic, atomic-free) ----------------
__global__ void combine(float* __restrict__ out) {
    __shared__ int soff[NEXP];
    int t = blockIdx.x, i = threadIdx.x;
    if (i == 0) {
        int o = 0;
        #pragma unroll
        for (int j = 0; j < NEXP; j++) { soff[j] = o; o += g_cnt[j]; }
    }
    __syncthreads();
    int a0 = g_tpe[t * 2], a1 = g_tpe[t * 2 + 1];
    float gA = g_tg[t * 2], gB = g_tg[t * 2 + 1];
    size_t r0 = (size_t)(soff[a0 >> 16] + (a0 & 0xFFFF)) * DIMX;
    size_t r1 = (size_t)(soff[a1 >> 16] + (a1 & 0xFFFF)) * DIMX;
    float4 v0 = ((const float4*)(g_y + r0))[i];
    float4 v1 = ((const float4*)(g_y + r1))[i];
    float4 o;
    o.x = v0.x * gA + v1.x * gB;
    o.y = v0.y * gA + v1.y * gB;
    o.z = v0.z * gA + v1.z * gB;
    o.w = v0.w * gA + v1.w * gB;
    ((float4*)(out + (size_t)t * DIMX))[i] = o;
}

// ---------------- launch ----------------
extern "C" void kernel_launch(void* const* d_in, const int* in_sizes, int n_in,
                              void* d_out, int out_size) {
    const float* x   = (const float*)d_in[0];
    const float* eps = (const float*)d_in[1];
    const float* wr  = (const float*)d_in[2];
    const float* wn  = (const float*)d_in[3];
    const float* w1  = (const float*)d_in[4];
    const float* w2  = (const float*)d_in[5];
    float* out = (float*)d_out;

    cudaFuncSetAttribute(bit_gemm<1>, cudaFuncAttributeMaxDynamicSharedMemorySize, GSMEM);
    cudaFuncSetAttribute(bit_gemm<2>, cudaFuncAttributeMaxDynamicSharedMemorySize, GSMEM);

    stats_partial<<<dim3(64, 18), 256>>>(wr, wn, w1, w2);       // 1
    finalize<<<1, 256>>>(wr, wn);                               // 2
    mega<<<dim3(32768, 1, 3), 256>>>(w1, w2, x, eps);           // 3
    bit_gemm<1><<<dim3(HIDX / BN, TTOK / BM, NEXP), 256, GSMEM>>>();   // 4 <- profiled
    h_quant<<<2 * TTOK, 256>>>();                               // 5
    bit_gemm<2><<<dim3(DIMX / BN, TTOK / BM, NEXP), 256, GSMEM>>>();   // 6
    combine<<<TTOK, 256>>>(out);                                // 7
}

// round 10
// speedup vs baseline: 1.0725x; 1.0725x over previous
#include <cuda_runtime.h>
#include <cstdint>

#define DIMX 1024
#define NEXP 8
#define HIDX 4096
#define TTOK 4096   // B*S = 2*2048

// ---------------- static scratch (no allocations allowed) ----------------
__device__ signed char g_wq1[(size_t)NEXP * HIDX * DIMX];   // ternary w1
__device__ signed char g_wq2[(size_t)NEXP * DIMX * HIDX];   // ternary w2
__device__ signed char g_wqr[NEXP * DIMX];
__device__ signed char g_wqn[NEXP * DIMX];
__device__ float g_partial[18 * 64];
__device__ float g_mval[18];
__device__ signed char g_xq[(size_t)TTOK * DIMX];
__device__ float g_deqx[TTOK];
__device__ int   g_cnt[NEXP];
__device__ int   g_tok[NEXP * TTOK];
__device__ int   g_tpe[TTOK * 2];    // (expert<<16)|pos per token slot
__device__ float g_tg[TTOK * 2];     // gates per token slot
__device__ float g_h[(size_t)2 * TTOK * HIDX];               // fp32 hidden
__device__ signed char g_hq[(size_t)2 * TTOK * HIDX];        // int8 hidden
__device__ float g_deqh[2 * TTOK];
__device__ float g_y[(size_t)2 * TTOK * DIMX];               // ungated expert outputs

// ---------------- helpers ----------------
__device__ __forceinline__ signed char terq(float x) {
    float r = rintf(x);
    r = fminf(1.f, fmaxf(-1.f, r));
    return (signed char)(int)r;
}
__device__ __forceinline__ signed char qi8(float x) {
    float r = rintf(x);
    r = fminf(127.f, fmaxf(-128.f, r));
    return (signed char)(int)r;
}
__device__ __forceinline__ uint32_t s2u(const void* p) {
    uint32_t a;
    asm("{ .reg .u64 t; cvta.to.shared.u64 t, %1; cvt.u32.u64 %0, t; }" : "=r"(a) : "l"(p));
    return a;
}
__device__ __forceinline__ void ldsm4(unsigned& r0, unsigned& r1, unsigned& r2, unsigned& r3,
                                      uint32_t a) {
    asm volatile("ldmatrix.sync.aligned.m8n8.x4.shared.b16 {%0,%1,%2,%3}, [%4];"
                 : "=r"(r0), "=r"(r1), "=r"(r2), "=r"(r3) : "r"(a));
}

// w2 ternarize slice: block `bid` covers float4 range [bid*1024, bid*1024+1024)
__device__ __forceinline__ void w2_slice(const float4* __restrict__ w2v, int bid, int tid) {
    size_t base = (size_t)bid * 1024;
    #pragma unroll
    for (int j = 0; j < 4; j++) {
        size_t i = base + tid + j * 256;
        int e = (int)(i >> 20);                 // 1048576 float4 per expert
        float sc = 1.0f / g_mval[10 + e];
        float4 v = w2v[i];
        char4 c;
        c.x = terq(v.x * sc); c.y = terq(v.y * sc);
        c.z = terq(v.z * sc); c.w = terq(v.w * sc);
        ((char4*)g_wq2)[i] = c;
    }
}

// ---------------- 1) weight stats: per-tensor sum |w| ----------------
__global__ void stats_partial(const float* __restrict__ wr, const float* __restrict__ wn,
                              const float* __restrict__ w1, const float* __restrict__ w2) {
    int slot = blockIdx.y, chunk = blockIdx.x;
    const float4* p;
    int nvec;
    if (slot < 2) {
        if (chunk != 0) return;
        p = (const float4*)(slot ? wn : wr);
        nvec = NEXP * DIMX / 4;
    } else if (slot < 10) {
        p = (const float4*)(w1 + (size_t)(slot - 2) * HIDX * DIMX) + (size_t)chunk * 16384;
        nvec = 16384;
    } else {
        p = (const float4*)(w2 + (size_t)(slot - 10) * DIMX * HIDX) + (size_t)chunk * 16384;
        nvec = 16384;
    }
    float s = 0.f;
    for (int i = threadIdx.x; i < nvec; i += 256) {
        float4 v = p[i];
        s += fabsf(v.x) + fabsf(v.y) + fabsf(v.z) + fabsf(v.w);
    }
    __shared__ float sh[8];
    #pragma unroll
    for (int o = 16; o; o >>= 1) s += __shfl_xor_sync(0xffffffffu, s, o);
    if ((threadIdx.x & 31) == 0) sh[threadIdx.x >> 5] = s;
    __syncthreads();
    if (threadIdx.x == 0) {
        float t = 0.f;
        #pragma unroll
        for (int j = 0; j < 8; j++) t += sh[j];
        g_partial[slot * 64 + chunk] = t;
    }
}

// ---------------- 2) finalize: mvals + small-weight ternarize + zero counts ----------------
__global__ void finalize(const float* __restrict__ wr, const float* __restrict__ wn) {
    int tid = threadIdx.x;
    __shared__ float sm[18];
    if (tid < 18) {
        int nc = (tid < 2) ? 1 : 64;
        float sum = 0.f;
        for (int c = 0; c < nc; c++) sum += g_partial[tid * 64 + c];
        float nelem = (tid < 2) ? (float)(NEXP * DIMX) : (float)((size_t)HIDX * DIMX);
        float m = fmaxf(sum / nelem, 1e-5f);
        g_mval[tid] = m;
        sm[tid] = m;
    }
    if (tid < NEXP) g_cnt[tid] = 0;
    __syncthreads();
    float sc0 = 1.0f / sm[0], sc1 = 1.0f / sm[1];
    for (int i = tid; i < NEXP * DIMX; i += 256) {
        g_wqr[i] = terq(wr[i] * sc0);
        g_wqn[i] = terq(wn[i] * sc1);
    }
}

// ---------------- 3) mega: w1 ternarize (z=0) + act-quant+router (z=1) ----------------
__global__ __launch_bounds__(256) void mega(const float* __restrict__ w1,
                                            const float* __restrict__ x,
                                            const float* __restrict__ eps) {
    int z = blockIdx.z;
    int tid = threadIdx.x;
    if (z == 0) {
        size_t i = (size_t)blockIdx.x * 256 + tid;   // float4 index, exactly covers w1
        int e = (int)(i >> 20);
        float sc = 1.0f / g_mval[2 + e];
        float4 v = ((const float4*)w1)[i];
        char4 c;
        c.x = terq(v.x * sc); c.y = terq(v.y * sc); c.z = terq(v.z * sc); c.w = terq(v.w * sc);
        ((char4*)g_wq1)[i] = c;
        return;
    }
    int t = blockIdx.x;
    if (t >= TTOK) return;

    __shared__ float shs[8], shm[8], svals[8], sdq[1];
    __shared__ int sx[256];

    float4 v = ((const float4*)(x + (size_t)t * DIMX))[tid];
    float ss = v.x * v.x + v.y * v.y + v.z * v.z + v.w * v.w;
    float am = fmaxf(fmaxf(fabsf(v.x), fabsf(v.y)), fmaxf(fabsf(v.z), fabsf(v.w)));
    #pragma unroll
    for (int o = 16; o; o >>= 1) {
        ss += __shfl_xor_sync(0xffffffffu, ss, o);
        am = fmaxf(am, __shfl_xor_sync(0xffffffffu, am, o));
    }
    if ((tid & 31) == 0) { shs[tid >> 5] = ss; shm[tid >> 5] = am; }
    __syncthreads();
    float tss = 0.f, tam = 0.f;
    #pragma unroll
    for (int j = 0; j < 8; j++) { tss += shs[j]; tam = fmaxf(tam, shm[j]); }
    float rs = rsqrtf(tss / (float)DIMX + 1e-6f);
    float a = fmaxf(tam * rs, 1e-5f);
    float sc = 127.0f / a;
    if (tid == 0) { g_deqx[t] = a / 127.0f; sdq[0] = a / 127.0f; }
    char4 c;
    c.x = qi8(v.x * rs * sc); c.y = qi8(v.y * rs * sc);
    c.z = qi8(v.z * rs * sc); c.w = qi8(v.w * rs * sc);
    ((char4*)(g_xq + (size_t)t * DIMX))[tid] = c;
    int ci;
    memcpy(&ci, &c, 4);
    sx[tid] = ci;
    __syncthreads();

    // router: warp w handles expert w
    int w = tid >> 5, lane = tid & 31;
    const int* wrp = (const int*)(g_wqr + w * DIMX);
    const int* wnp = (const int*)(g_wqn + w * DIMX);
    int ar = 0, an = 0;
    #pragma unroll
    for (int j = 0; j < 8; j++) {
        int xi = sx[lane + 32 * j];
        ar = __dp4a(xi, wrp[lane + 32 * j], ar);
        an = __dp4a(xi, wnp[lane + 32 * j], an);
    }
    #pragma unroll
    for (int o = 16; o; o >>= 1) {
        ar += __shfl_xor_sync(0xffffffffu, ar, o);
        an += __shfl_xor_sync(0xffffffffu, an, o);
    }
    if (lane == 0) {
        float dq = sdq[0];
        float lg = (float)ar * dq * g_mval[0];
        float nl = (float)an * dq * g_mval[1];
        float sp = fmaxf(nl, 0.f) + log1pf(expf(-fabsf(nl)));
        svals[w] = lg + eps[t * NEXP + w] * sp;
    }
    __syncthreads();
    if (tid == 0) {
        float v0 = -1e30f, v1 = -1e30f;
        int i0 = 0, i1 = 0;
        #pragma unroll
        for (int e = 0; e < NEXP; e++) {
            float vv = svals[e];
            if (vv > v0) { v1 = v0; i1 = i0; v0 = vv; i0 = e; }
            else if (vv > v1) { v1 = vv; i1 = e; }
        }
        float ex = expf(v1 - v0);
        float inv = 1.0f / (1.0f + ex);
        int p0 = atomicAdd(&g_cnt[i0], 1);
        g_tok[i0 * TTOK + p0] = t;
        int p1 = atomicAdd(&g_cnt[i1], 1);
        g_tok[i1 * TTOK + p1] = t;
        g_tpe[t * 2]     = (i0 << 16) | p0;
        g_tpe[t * 2 + 1] = (i1 << 16) | p1;
        g_tg[t * 2]      = inv;
        g_tg[t * 2 + 1]  = ex * inv;
    }
}

// ---------------- 4/6) pipelined int8 tensor-core grouped GEMM ----------------
// Tile 128x128, BKK=64, 3-stage cp.async pipeline, 3 blocks/SM (forced via
// launch_bounds), two barriers per K-iter (wait_group is per-thread; barrier
// after the wait publishes all threads' stage-i copies).
#define BM 128
#define BN 128
#define BKK 64
#define LDSS 80          // 64 + 16 pad: conflict-free ldmatrix phases
#define STG_STRIDE (2 * BM * LDSS)   // A stage + B stage = 20480
#define GSMEM (3 * STG_STRIDE)       // 3 stages = 61440 B

__device__ __forceinline__ void mma8(int (&c)[4], const unsigned (&a)[4], const unsigned (&b)[2]) {
    asm volatile(
        "mma.sync.aligned.m16n8k32.row.col.s32.s8.s8.s32 "
        "{%0,%1,%2,%3}, {%4,%5,%6,%7}, {%8,%9}, {%0,%1,%2,%3};\n"
        : "+r"(c[0]), "+r"(c[1]), "+r"(c[2]), "+r"(c[3])
        : "r"(a[0]), "r"(a[1]), "r"(a[2]), "r"(a[3]), "r"(b[0]), "r"(b[1]));
}

template <int MODE>
__global__ __launch_bounds__(256, 3) void bit_gemm(const float* __restrict__ w2fp) {
    constexpr int K = (MODE == 1) ? DIMX : HIDX;
    constexpr int N = (MODE == 1) ? HIDX : DIMX;
    constexpr int NITER = K / BKK;
    const int e = blockIdx.z;
    const int cnt = g_cnt[e];
    const int m0 = blockIdx.y * BM;
    const int tid = threadIdx.x;
    if (m0 >= cnt) {
        if (MODE == 1) {
            int bid = blockIdx.x + (int)gridDim.x * (blockIdx.y + (int)gridDim.y * blockIdx.z);
            w2_slice((const float4*)w2fp, bid, tid);
        }
        return;
    }
    const int n0 = blockIdx.x * BN;
    int off = 0;
    #pragma unroll
    for (int j = 0; j < NEXP; j++) if (j < e) off += g_cnt[j];

    extern __shared__ char dsm[];
    const uint32_t smb = s2u(dsm);

    const int lane = tid & 31, warp = tid >> 5;
    const int wm = warp >> 2, wn = warp & 3;   // 2x4 warp grid, warp tile 64x32

    int acc[4][4][4];
    #pragma unroll
    for (int a = 0; a < 4; a++)
        #pragma unroll
        for (int b = 0; b < 4; b++)
            #pragma unroll
            for (int c = 0; c < 4; c++) acc[a][b][c] = 0;

    const int lr = tid >> 1;            // staged row (0..127)
    const int lcb = (tid & 1) * 32;     // byte offset within 64B k-chunk
    const bool aok = (m0 + lr) < cnt;
    const signed char* Ap;
    if (MODE == 1) {
        int tok = aok ? g_tok[e * TTOK + m0 + lr] : 0;
        Ap = g_xq + (size_t)tok * K + lcb;
    } else {
        int r = aok ? (off + m0 + lr) : 0;
        Ap = g_hq + (size_t)r * K + lcb;
    }
    const unsigned aSz = aok ? 16u : 0u;
    const signed char* wsrc = (MODE == 1) ? g_wq1 : g_wq2;
    const signed char* Bp = wsrc + (size_t)e * N * K + (size_t)(n0 + lr) * K + lcb;

    const uint32_t cpOff = (uint32_t)(lr * LDSS + lcb);
    // ldmatrix lane offsets
    const uint32_t aLO = (uint32_t)((lane & 15) * LDSS + (lane >> 4) * 16);
    const uint32_t bLO = (uint32_t)(((lane >> 4) * 8 + (lane & 7)) * LDSS + ((lane >> 3) & 1) * 16);

    auto prefetch = [&](int it) {
        int s = it;
        while (s >= 3) s -= 3;
        uint32_t ab = smb + s * STG_STRIDE + cpOff;
        uint32_t bb = ab + BM * LDSS;
        const signed char* as = Ap;
        const signed char* bs = Bp;
        unsigned asz = 0, bsz = 0;
        if (it < NITER) {
            as = Ap + it * BKK;
            bs = Bp + it * BKK;
            asz = aSz;
            bsz = 16;
        }
        asm volatile("cp.async.cg.shared.global [%0], [%1], 16, %2;"
                     :: "r"(ab), "l"(as), "r"(asz) : "memory");
        asm volatile("cp.async.cg.shared.global [%0], [%1], 16, %2;"
                     :: "r"(ab + 16), "l"(as + 16), "r"(asz) : "memory");
        asm volatile("cp.async.cg.shared.global [%0], [%1], 16, %2;"
                     :: "r"(bb), "l"(bs), "r"(bsz) : "memory");
        asm volatile("cp.async.cg.shared.global [%0], [%1], 16, %2;"
                     :: "r"(bb + 16), "l"(bs + 16), "r"(bsz) : "memory");
        asm volatile("cp.async.commit_group;" ::: "memory");
    };

    prefetch(0);
    prefetch(1);
    #pragma unroll 1
    for (int i = 0; i < NITER; i++) {
        // stage (i+2)%3 == (i-1)%3 was released by the trailing barrier of iter i-1
        prefetch(i + 2);
        asm volatile("cp.async.wait_group 2;" ::: "memory");   // my group-i copies landed
        __syncthreads();                                       // everyone's group-i copies landed
        int s = i;
        while (s >= 3) s -= 3;
        const uint32_t aB = smb + s * STG_STRIDE;
        const uint32_t bB = aB + BM * LDSS;
        #pragma unroll
        for (int ks = 0; ks < 2; ks++) {
            unsigned af[4][4];
            #pragma unroll
            for (int mi = 0; mi < 4; mi++)
                ldsm4(af[mi][0], af[mi][1], af[mi][2], af[mi][3],
                      aB + (uint32_t)((wm * 64 + mi * 16) * LDSS + ks * 32) + aLO);
            unsigned bf[4][2];
            #pragma unroll
            for (int np = 0; np < 2; np++)
                ldsm4(bf[np * 2][0], bf[np * 2][1], bf[np * 2 + 1][0], bf[np * 2 + 1][1],
                      bB + (uint32_t)((wn * 32 + np * 16) * LDSS + ks * 32) + bLO);
            #pragma unroll
            for (int mi = 0; mi < 4; mi++)
                #pragma unroll
                for (int ni = 0; ni < 4; ni++) mma8(acc[mi][ni], af[mi], bf[ni]);
        }
        __syncthreads();                                       // release stage i for reuse
    }

    if (MODE == 1) {
        const float m1 = g_mval[2 + e];
        #pragma unroll
        for (int mi = 0; mi < 4; mi++) {
            #pragma unroll
            for (int half = 0; half < 2; half++) {
                int rrow = wm * 64 + mi * 16 + (lane >> 2) + half * 8;
                int pos = m0 + rrow;
                if (pos < cnt) {
                    float d = g_deqx[g_tok[e * TTOK + pos]] * m1;
                    float* hrow = g_h + (size_t)(off + pos) * HIDX + n0;
                    #pragma unroll
                    for (int ni = 0; ni < 4; ni++) {
                        int col = wn * 32 + ni * 8 + (lane & 3) * 2;
                        float2 v;
                        v.x = fmaxf(0.f, (float)acc[mi][ni][half * 2 + 0] * d);
                        v.y = fmaxf(0.f, (float)acc[mi][ni][half * 2 + 1] * d);
                        *(float2*)(hrow + col) = v;
                    }
                }
            }
        }
        // this block's w2 ternarize slice (overlaps with other blocks' MMA work)
        int bid = blockIdx.x + (int)gridDim.x * (blockIdx.y + (int)gridDim.y * blockIdx.z);
        w2_slice((const float4*)w2fp, bid, tid);
    } else {
        const float m2 = g_mval[10 + e];
        #pragma unroll
        for (int mi = 0; mi < 4; mi++) {
            #pragma unroll
            for (int half = 0; half < 2; half++) {
                int rrow = wm * 64 + mi * 16 + (lane >> 2) + half * 8;
                int pos = m0 + rrow;
                if (pos < cnt) {
                    float d = g_deqh[off + pos] * m2;
                    float* yrow = g_y + (size_t)(off + pos) * DIMX + n0;
                    #pragma unroll
                    for (int ni = 0; ni < 4; ni++) {
                        int col = wn * 32 + ni * 8 + (lane & 3) * 2;
                        float2 v;
                        v.x = (float)acc[mi][ni][half * 2 + 0] * d;
                        v.y = (float)acc[mi][ni][half * 2 + 1] * d;
                        *(float2*)(yrow + col) = v;
                    }
                }
            }
        }
    }
}

// ---------------- 5) hidden quant: one block per packed row ----------------
__global__ void h_quant() {
    size_t row = blockIdx.x;   // 0 .. 2*TTOK-1 (all slots always filled)
    const float4* hp = (const float4*)(g_h + row * HIDX);
    int tid = threadIdx.x;
    float4 r[4];
    float ss = 0.f, am = 0.f;
    #pragma unroll
    for (int j = 0; j < 4; j++) {
        r[j] = hp[tid + 256 * j];
        ss += r[j].x * r[j].x + r[j].y * r[j].y + r[j].z * r[j].z + r[j].w * r[j].w;
        am = fmaxf(am, fmaxf(fmaxf(fabsf(r[j].x), fabsf(r[j].y)), fmaxf(fabsf(r[j].z), fabsf(r[j].w))));
    }
    __shared__ float shs[8], shm[8];
    #pragma unroll
    for (int o = 16; o; o >>= 1) {
        ss += __shfl_xor_sync(0xffffffffu, ss, o);
        am = fmaxf(am, __shfl_xor_sync(0xffffffffu, am, o));
    }
    if ((tid & 31) == 0) { shs[tid >> 5] = ss; shm[tid >> 5] = am; }
    __syncthreads();
    float tss = 0.f, tam = 0.f;
    #pragma unroll
    for (int j = 0; j < 8; j++) { tss += shs[j]; tam = fmaxf(tam, shm[j]); }
    float rs = rsqrtf(tss / (float)HIDX + 1e-6f);
    float a = fmaxf(tam * rs, 1e-5f);
    float sc = 127.0f / a;
    if (tid == 0) g_deqh[row] = a / 127.0f;
    char4* dst = (char4*)(g_hq + row * HIDX);
    #pragma unroll
    for (int j = 0; j < 4; j++) {
        char4 c;
        c.x = qi8(r[j].x * rs * sc); c.y = qi8(r[j].y * rs * sc);
        c.z = qi8(r[j].z * rs * sc); c.w = qi8(r[j].w * rs * sc);
        dst[tid + 256 * j] = c;
    }
}

// ---------------- 7) gated combine (deterministic, atomic-free) ----------------
__global__ void combine(float* __restrict__ out) {
    __shared__ int soff[NEXP];
    int t = blockIdx.x, i = threadIdx.x;
    if (i == 0) {
        int o = 0;
        #pragma unroll
        for (int j = 0; j < NEXP; j++) { soff[j] = o; o += g_cnt[j]; }
    }
    __syncthreads();
    int a0 = g_tpe[t * 2], a1 = g_tpe[t * 2 + 1];
    float gA = g_tg[t * 2], gB = g_tg[t * 2 + 1];
    size_t r0 = (size_t)(soff[a0 >> 16] + (a0 & 0xFFFF)) * DIMX;
    size_t r1 = (size_t)(soff[a1 >> 16] + (a1 & 0xFFFF)) * DIMX;
    float4 v0 = ((const float4*)(g_y + r0))[i];
    float4 v1 = ((const float4*)(g_y + r1))[i];
    float4 o;
    o.x = v0.x * gA + v1.x * gB;
    o.y = v0.y * gA + v1.y * gB;
    o.z = v0.z * gA + v1.z * gB;
    o.w = v0.w * gA + v1.w * gB;
    ((float4*)(out + (size_t)t * DIMX))[i] = o;
}

// ---------------- launch ----------------
extern "C" void kernel_launch(void* const* d_in, const int* in_sizes, int n_in,
                              void* d_out, int out_size) {
    const float* x   = (const float*)d_in[0];
    const float* eps = (const float*)d_in[1];
    const float* wr  = (const float*)d_in[2];
    const float* wn  = (const float*)d_in[3];
    const float* w1  = (const float*)d_in[4];
    const float* w2  = (const float*)d_in[5];
    float* out = (float*)d_out;

    cudaFuncSetAttribute(bit_gemm<1>, cudaFuncAttributeMaxDynamicSharedMemorySize, GSMEM);
    cudaFuncSetAttribute(bit_gemm<2>, cudaFuncAttributeMaxDynamicSharedMemorySize, GSMEM);

    stats_partial<<<dim3(64, 18), 256>>>(wr, wn, w1, w2);       // 1
    finalize<<<1, 256>>>(wr, wn);                               // 2
    mega<<<dim3(32768, 1, 2), 256>>>(w1, x, eps);               // 3
    bit_gemm<1><<<dim3(HIDX / BN, TTOK / BM, NEXP), 256, GSMEM>>>(w2);   // 4 <- profiled
    h_quant<<<2 * TTOK, 256>>>();                               // 5
    bit_gemm<2><<<dim3(DIMX / BN, TTOK / BM, NEXP), 256, GSMEM>>>(nullptr);  // 6
    combine<<<TTOK, 256>>>(out);                                // 7
}

// round 11
// speedup vs baseline: 1.0750x; 1.0023x over previous
#include <cuda_runtime.h>
#include <cstdint>

#define DIMX 1024
#define NEXP 8
#define HIDX 4096
#define TTOK 4096   // B*S = 2*2048

// ---------------- static scratch (no allocations allowed) ----------------
__device__ signed char g_wq1[(size_t)NEXP * HIDX * DIMX];   // ternary w1
__device__ signed char g_wq2[(size_t)NEXP * DIMX * HIDX];   // ternary w2
__device__ signed char g_wqr[NEXP * DIMX];
__device__ signed char g_wqn[NEXP * DIMX];
__device__ float g_partial[18 * 64];
__device__ float g_mval[18];
__device__ signed char g_xq[(size_t)TTOK * DIMX];
__device__ float g_deqx[TTOK];
__device__ int   g_cnt[NEXP];
__device__ int   g_tok[NEXP * TTOK];
__device__ int   g_tpe[TTOK * 2];    // (expert<<16)|pos per token slot
__device__ float g_tg[TTOK * 2];     // gates per token slot
__device__ float g_h[(size_t)2 * TTOK * HIDX];               // fp32 hidden
__device__ signed char g_hq[(size_t)2 * TTOK * HIDX];        // int8 hidden
__device__ float g_deqh[2 * TTOK];
__device__ int g_yp0[(size_t)2 * TTOK * DIMX];               // int32 partial (K half 0)
__device__ int g_yp1[(size_t)2 * TTOK * DIMX];               // int32 partial (K half 1)

// ---------------- helpers ----------------
__device__ __forceinline__ signed char terq(float x) {
    float r = rintf(x);
    r = fminf(1.f, fmaxf(-1.f, r));
    return (signed char)(int)r;
}
__device__ __forceinline__ signed char qi8(float x) {
    float r = rintf(x);
    r = fminf(127.f, fmaxf(-128.f, r));
    return (signed char)(int)r;
}
__device__ __forceinline__ uint32_t s2u(const void* p) {
    uint32_t a;
    asm("{ .reg .u64 t; cvta.to.shared.u64 t, %1; cvt.u32.u64 %0, t; }" : "=r"(a) : "l"(p));
    return a;
}
__device__ __forceinline__ void ldsm4(unsigned& r0, unsigned& r1, unsigned& r2, unsigned& r3,
                                      uint32_t a) {
    asm volatile("ldmatrix.sync.aligned.m8n8.x4.shared.b16 {%0,%1,%2,%3}, [%4];"
                 : "=r"(r0), "=r"(r1), "=r"(r2), "=r"(r3) : "r"(a));
}

// w2 ternarize slice: block `bid` covers float4 range [bid*1024, bid*1024+1024)
__device__ __forceinline__ void w2_slice(const float4* __restrict__ w2v, int bid, int tid) {
    size_t base = (size_t)bid * 1024;
    #pragma unroll
    for (int j = 0; j < 4; j++) {
        size_t i = base + tid + j * 256;
        int e = (int)(i >> 20);                 // 1048576 float4 per expert
        float sc = 1.0f / g_mval[10 + e];
        float4 v = w2v[i];
        char4 c;
        c.x = terq(v.x * sc); c.y = terq(v.y * sc);
        c.z = terq(v.z * sc); c.w = terq(v.w * sc);
        ((char4*)g_wq2)[i] = c;
    }
}

// ---------------- 1) weight stats: per-tensor sum |w| ----------------
__global__ void stats_partial(const float* __restrict__ wr, const float* __restrict__ wn,
                              const float* __restrict__ w1, const float* __restrict__ w2) {
    int slot = blockIdx.y, chunk = blockIdx.x;
    const float4* p;
    int nvec;
    if (slot < 2) {
        if (chunk != 0) return;
        p = (const float4*)(slot ? wn : wr);
        nvec = NEXP * DIMX / 4;
    } else if (slot < 10) {
        p = (const float4*)(w1 + (size_t)(slot - 2) * HIDX * DIMX) + (size_t)chunk * 16384;
        nvec = 16384;
    } else {
        p = (const float4*)(w2 + (size_t)(slot - 10) * DIMX * HIDX) + (size_t)chunk * 16384;
        nvec = 16384;
    }
    float s = 0.f;
    for (int i = threadIdx.x; i < nvec; i += 256) {
        float4 v = p[i];
        s += fabsf(v.x) + fabsf(v.y) + fabsf(v.z) + fabsf(v.w);
    }
    __shared__ float sh[8];
    #pragma unroll
    for (int o = 16; o; o >>= 1) s += __shfl_xor_sync(0xffffffffu, s, o);
    if ((threadIdx.x & 31) == 0) sh[threadIdx.x >> 5] = s;
    __syncthreads();
    if (threadIdx.x == 0) {
        float t = 0.f;
        #pragma unroll
        for (int j = 0; j < 8; j++) t += sh[j];
        g_partial[slot * 64 + chunk] = t;
    }
}

// ---------------- 2) finalize: mvals + small-weight ternarize + zero counts ----------------
__global__ void finalize(const float* __restrict__ wr, const float* __restrict__ wn) {
    int tid = threadIdx.x;
    __shared__ float sm[18];
    if (tid < 18) {
        int nc = (tid < 2) ? 1 : 64;
        float sum = 0.f;
        for (int c = 0; c < nc; c++) sum += g_partial[tid * 64 + c];
        float nelem = (tid < 2) ? (float)(NEXP * DIMX) : (float)((size_t)HIDX * DIMX);
        float m = fmaxf(sum / nelem, 1e-5f);
        g_mval[tid] = m;
        sm[tid] = m;
    }
    if (tid < NEXP) g_cnt[tid] = 0;
    __syncthreads();
    float sc0 = 1.0f / sm[0], sc1 = 1.0f / sm[1];
    for (int i = tid; i < NEXP * DIMX; i += 256) {
        g_wqr[i] = terq(wr[i] * sc0);
        g_wqn[i] = terq(wn[i] * sc1);
    }
}

// ---------------- 3) mega: w1 ternarize (z=0) + act-quant+router (z=1) ----------------
__global__ __launch_bounds__(256) void mega(const float* __restrict__ w1,
                                            const float* __restrict__ x,
                                            const float* __restrict__ eps) {
    int z = blockIdx.z;
    int tid = threadIdx.x;
    if (z == 0) {
        size_t i = (size_t)blockIdx.x * 256 + tid;   // float4 index, exactly covers w1
        int e = (int)(i >> 20);
        float sc = 1.0f / g_mval[2 + e];
        float4 v = ((const float4*)w1)[i];
        char4 c;
        c.x = terq(v.x * sc); c.y = terq(v.y * sc); c.z = terq(v.z * sc); c.w = terq(v.w * sc);
        ((char4*)g_wq1)[i] = c;
        return;
    }
    int t = blockIdx.x;
    if (t >= TTOK) return;

    __shared__ float shs[8], shm[8], svals[8], sdq[1];
    __shared__ int sx[256];

    float4 v = ((const float4*)(x + (size_t)t * DIMX))[tid];
    float ss = v.x * v.x + v.y * v.y + v.z * v.z + v.w * v.w;
    float am = fmaxf(fmaxf(fabsf(v.x), fabsf(v.y)), fmaxf(fabsf(v.z), fabsf(v.w)));
    #pragma unroll
    for (int o = 16; o; o >>= 1) {
        ss += __shfl_xor_sync(0xffffffffu, ss, o);
        am = fmaxf(am, __shfl_xor_sync(0xffffffffu, am, o));
    }
    if ((tid & 31) == 0) { shs[tid >> 5] = ss; shm[tid >> 5] = am; }
    __syncthreads();
    float tss = 0.f, tam = 0.f;
    #pragma unroll
    for (int j = 0; j < 8; j++) { tss += shs[j]; tam = fmaxf(tam, shm[j]); }
    float rs = rsqrtf(tss / (float)DIMX + 1e-6f);
    float a = fmaxf(tam * rs, 1e-5f);
    float sc = 127.0f / a;
    if (tid == 0) { g_deqx[t] = a / 127.0f; sdq[0] = a / 127.0f; }
    char4 c;
    c.x = qi8(v.x * rs * sc); c.y = qi8(v.y * rs * sc);
    c.z = qi8(v.z * rs * sc); c.w = qi8(v.w * rs * sc);
    ((char4*)(g_xq + (size_t)t * DIMX))[tid] = c;
    int ci;
    memcpy(&ci, &c, 4);
    sx[tid] = ci;
    __syncthreads();

    // router: warp w handles expert w
    int w = tid >> 5, lane = tid & 31;
    const int* wrp = (const int*)(g_wqr + w * DIMX);
    const int* wnp = (const int*)(g_wqn + w * DIMX);
    int ar = 0, an = 0;
    #pragma unroll
    for (int j = 0; j < 8; j++) {
        int xi = sx[lane + 32 * j];
        ar = __dp4a(xi, wrp[lane + 32 * j], ar);
        an = __dp4a(xi, wnp[lane + 32 * j], an);
    }
    #pragma unroll
    for (int o = 16; o; o >>= 1) {
        ar += __shfl_xor_sync(0xffffffffu, ar, o);
        an += __shfl_xor_sync(0xffffffffu, an, o);
    }
    if (lane == 0) {
        float dq = sdq[0];
        float lg = (float)ar * dq * g_mval[0];
        float nl = (float)an * dq * g_mval[1];
        float sp = fmaxf(nl, 0.f) + log1pf(expf(-fabsf(nl)));
        svals[w] = lg + eps[t * NEXP + w] * sp;
    }
    __syncthreads();
    if (tid == 0) {
        float v0 = -1e30f, v1 = -1e30f;
        int i0 = 0, i1 = 0;
        #pragma unroll
        for (int e = 0; e < NEXP; e++) {
            float vv = svals[e];
            if (vv > v0) { v1 = v0; i1 = i0; v0 = vv; i0 = e; }
            else if (vv > v1) { v1 = vv; i1 = e; }
        }
        float ex = expf(v1 - v0);
        float inv = 1.0f / (1.0f + ex);
        int p0 = atomicAdd(&g_cnt[i0], 1);
        g_tok[i0 * TTOK + p0] = t;
        int p1 = atomicAdd(&g_cnt[i1], 1);
        g_tok[i1 * TTOK + p1] = t;
        g_tpe[t * 2]     = (i0 << 16) | p0;
        g_tpe[t * 2 + 1] = (i1 << 16) | p1;
        g_tg[t * 2]      = inv;
        g_tg[t * 2 + 1]  = ex * inv;
    }
}

// ---------------- 4/6) pipelined int8 tensor-core grouped GEMM ----------------
// Tile 128x128, BKK=64, 3-stage cp.async pipeline, 3 blocks/SM.
// MODE 2 uses a deterministic K-split (2 halves -> int32 partial buffers):
// doubles live blocks to fix the 1.3-wave tail; int accumulation is exact,
// so summation in `combine` is bit-deterministic.
#define BM 128
#define BN 128
#define BKK 64
#define LDSS 80          // 64 + 16 pad: conflict-free ldmatrix phases
#define STG_STRIDE (2 * BM * LDSS)   // A stage + B stage = 20480
#define GSMEM (3 * STG_STRIDE)       // 3 stages = 61440 B

__device__ __forceinline__ void mma8(int (&c)[4], const unsigned (&a)[4], const unsigned (&b)[2]) {
    asm volatile(
        "mma.sync.aligned.m16n8k32.row.col.s32.s8.s8.s32 "
        "{%0,%1,%2,%3}, {%4,%5,%6,%7}, {%8,%9}, {%0,%1,%2,%3};\n"
        : "+r"(c[0]), "+r"(c[1]), "+r"(c[2]), "+r"(c[3])
        : "r"(a[0]), "r"(a[1]), "r"(a[2]), "r"(a[3]), "r"(b[0]), "r"(b[1]));
}

template <int MODE>
__global__ __launch_bounds__(256, 3) void bit_gemm(const float* __restrict__ w2fp) {
    constexpr int K = (MODE == 1) ? DIMX : HIDX;          // full row stride
    constexpr int KRUN = (MODE == 1) ? DIMX : HIDX / 2;   // K covered per block
    constexpr int N = (MODE == 1) ? HIDX : DIMX;
    constexpr int NITER = KRUN / BKK;
    const int e = (MODE == 1) ? blockIdx.z : (blockIdx.z & 7);
    const int ksp = (MODE == 1) ? 0 : (blockIdx.z >> 3);
    const int kbase = ksp * KRUN;
    const int cnt = g_cnt[e];
    const int m0 = blockIdx.y * BM;
    const int tid = threadIdx.x;
    if (m0 >= cnt) {
        if (MODE == 1) {
            int bid = blockIdx.x + (int)gridDim.x * (blockIdx.y + (int)gridDim.y * blockIdx.z);
            w2_slice((const float4*)w2fp, bid, tid);
        }
        return;
    }
    const int n0 = blockIdx.x * BN;
    int off = 0;
    #pragma unroll
    for (int j = 0; j < NEXP; j++) if (j < e) off += g_cnt[j];

    extern __shared__ char dsm[];
    const uint32_t smb = s2u(dsm);

    const int lane = tid & 31, warp = tid >> 5;
    const int wm = warp >> 2, wn = warp & 3;   // 2x4 warp grid, warp tile 64x32

    int acc[4][4][4];
    #pragma unroll
    for (int a = 0; a < 4; a++)
        #pragma unroll
        for (int b = 0; b < 4; b++)
            #pragma unroll
            for (int c = 0; c < 4; c++) acc[a][b][c] = 0;

    const int lr = tid >> 1;            // staged row (0..127)
    const int lcb = (tid & 1) * 32;     // byte offset within 64B k-chunk
    const bool aok = (m0 + lr) < cnt;
    const signed char* Ap;
    if (MODE == 1) {
        int tok = aok ? g_tok[e * TTOK + m0 + lr] : 0;
        Ap = g_xq + (size_t)tok * K + kbase + lcb;
    } else {
        int r = aok ? (off + m0 + lr) : 0;
        Ap = g_hq + (size_t)r * K + kbase + lcb;
    }
    const unsigned aSz = aok ? 16u : 0u;
    const signed char* wsrc = (MODE == 1) ? g_wq1 : g_wq2;
    const signed char* Bp = wsrc + (size_t)e * N * K + (size_t)(n0 + lr) * K + kbase + lcb;

    const uint32_t cpOff = (uint32_t)(lr * LDSS + lcb);
    // ldmatrix lane offsets
    const uint32_t aLO = (uint32_t)((lane & 15) * LDSS + (lane >> 4) * 16);
    const uint32_t bLO = (uint32_t)(((lane >> 4) * 8 + (lane & 7)) * LDSS + ((lane >> 3) & 1) * 16);

    auto prefetch = [&](int it) {
        int s = it;
        while (s >= 3) s -= 3;
        uint32_t ab = smb + s * STG_STRIDE + cpOff;
        uint32_t bb = ab + BM * LDSS;
        const signed char* as = Ap;
        const signed char* bs = Bp;
        unsigned asz = 0, bsz = 0;
        if (it < NITER) {
            as = Ap + it * BKK;
            bs = Bp + it * BKK;
            asz = aSz;
            bsz = 16;
        }
        asm volatile("cp.async.cg.shared.global [%0], [%1], 16, %2;"
                     :: "r"(ab), "l"(as), "r"(asz) : "memory");
        asm volatile("cp.async.cg.shared.global [%0], [%1], 16, %2;"
                     :: "r"(ab + 16), "l"(as + 16), "r"(asz) : "memory");
        asm volatile("cp.async.cg.shared.global [%0], [%1], 16, %2;"
                     :: "r"(bb), "l"(bs), "r"(bsz) : "memory");
        asm volatile("cp.async.cg.shared.global [%0], [%1], 16, %2;"
                     :: "r"(bb + 16), "l"(bs + 16), "r"(bsz) : "memory");
        asm volatile("cp.async.commit_group;" ::: "memory");
    };

    prefetch(0);
    prefetch(1);
    #pragma unroll 1
    for (int i = 0; i < NITER; i++) {
        // stage (i+2)%3 == (i-1)%3 was released by the trailing barrier of iter i-1
        prefetch(i + 2);
        asm volatile("cp.async.wait_group 2;" ::: "memory");   // my group-i copies landed
        __syncthreads();                                       // everyone's group-i copies landed
        int s = i;
        while (s >= 3) s -= 3;
        const uint32_t aB = smb + s * STG_STRIDE;
        const uint32_t bB = aB + BM * LDSS;
        #pragma unroll
        for (int ks = 0; ks < 2; ks++) {
            unsigned af[4][4];
            #pragma unroll
            for (int mi = 0; mi < 4; mi++)
                ldsm4(af[mi][0], af[mi][1], af[mi][2], af[mi][3],
                      aB + (uint32_t)((wm * 64 + mi * 16) * LDSS + ks * 32) + aLO);
            unsigned bf[4][2];
            #pragma unroll
            for (int np = 0; np < 2; np++)
                ldsm4(bf[np * 2][0], bf[np * 2][1], bf[np * 2 + 1][0], bf[np * 2 + 1][1],
                      bB + (uint32_t)((wn * 32 + np * 16) * LDSS + ks * 32) + bLO);
            #pragma unroll
            for (int mi = 0; mi < 4; mi++)
                #pragma unroll
                for (int ni = 0; ni < 4; ni++) mma8(acc[mi][ni], af[mi], bf[ni]);
        }
        __syncthreads();                                       // release stage i for reuse
    }

    if (MODE == 1) {
        const float m1 = g_mval[2 + e];
        #pragma unroll
        for (int mi = 0; mi < 4; mi++) {
            #pragma unroll
            for (int half = 0; half < 2; half++) {
                int rrow = wm * 64 + mi * 16 + (lane >> 2) + half * 8;
                int pos = m0 + rrow;
                if (pos < cnt) {
                    float d = g_deqx[g_tok[e * TTOK + pos]] * m1;
                    float* hrow = g_h + (size_t)(off + pos) * HIDX + n0;
                    #pragma unroll
                    for (int ni = 0; ni < 4; ni++) {
                        int col = wn * 32 + ni * 8 + (lane & 3) * 2;
                        float2 v;
                        v.x = fmaxf(0.f, (float)acc[mi][ni][half * 2 + 0] * d);
                        v.y = fmaxf(0.f, (float)acc[mi][ni][half * 2 + 1] * d);
                        *(float2*)(hrow + col) = v;
                    }
                }
            }
        }
        // this block's w2 ternarize slice (overlaps with other blocks' MMA work)
        int bid = blockIdx.x + (int)gridDim.x * (blockIdx.y + (int)gridDim.y * blockIdx.z);
        w2_slice((const float4*)w2fp, bid, tid);
    } else {
        int* yp = ksp ? g_yp1 : g_yp0;
        #pragma unroll
        for (int mi = 0; mi < 4; mi++) {
            #pragma unroll
            for (int half = 0; half < 2; half++) {
                int rrow = wm * 64 + mi * 16 + (lane >> 2) + half * 8;
                int pos = m0 + rrow;
                if (pos < cnt) {
                    int* yrow = yp + (size_t)(off + pos) * DIMX + n0;
                    #pragma unroll
                    for (int ni = 0; ni < 4; ni++) {
                        int col = wn * 32 + ni * 8 + (lane & 3) * 2;
                        int2 v;
                        v.x = acc[mi][ni][half * 2 + 0];
                        v.y = acc[mi][ni][half * 2 + 1];
                        *(int2*)(yrow + col) = v;
                    }
                }
            }
        }
    }
}

// ---------------- 5) hidden quant: one block per packed row ----------------
__global__ void h_quant() {
    size_t row = blockIdx.x;   // 0 .. 2*TTOK-1 (all slots always filled)
    const float4* hp = (const float4*)(g_h + row * HIDX);
    int tid = threadIdx.x;
    float4 r[4];
    float ss = 0.f, am = 0.f;
    #pragma unroll
    for (int j = 0; j < 4; j++) {
        r[j] = hp[tid + 256 * j];
        ss += r[j].x * r[j].x + r[j].y * r[j].y + r[j].z * r[j].z + r[j].w * r[j].w;
        am = fmaxf(am, fmaxf(fmaxf(fabsf(r[j].x), fabsf(r[j].y)), fmaxf(fabsf(r[j].z), fabsf(r[j].w))));
    }
    __shared__ float shs[8], shm[8];
    #pragma unroll
    for (int o = 16; o; o >>= 1) {
        ss += __shfl_xor_sync(0xffffffffu, ss, o);
        am = fmaxf(am, __shfl_xor_sync(0xffffffffu, am, o));
    }
    if ((tid & 31) == 0) { shs[tid >> 5] = ss; shm[tid >> 5] = am; }
    __syncthreads();
    float tss = 0.f, tam = 0.f;
    #pragma unroll
    for (int j = 0; j < 8; j++) { tss += shs[j]; tam = fmaxf(tam, shm[j]); }
    float rs = rsqrtf(tss / (float)HIDX + 1e-6f);
    float a = fmaxf(tam * rs, 1e-5f);
    float sc = 127.0f / a;
    if (tid == 0) g_deqh[row] = a / 127.0f;
    char4* dst = (char4*)(g_hq + row * HIDX);
    #pragma unroll
    for (int j = 0; j < 4; j++) {
        char4 c;
        c.x = qi8(r[j].x * rs * sc); c.y = qi8(r[j].y * rs * sc);
        c.z = qi8(r[j].z * rs * sc); c.w = qi8(r[j].w * rs * sc);
        dst[tid + 256 * j] = c;
    }
}

// ---------------- 7) gated combine (deterministic, atomic-free) ----------------
__global__ void combine(float* __restrict__ out) {
    __shared__ int soff[NEXP];
    int t = blockIdx.x, i = threadIdx.x;
    if (i == 0) {
        int o = 0;
        #pragma unroll
        for (int j = 0; j < NEXP; j++) { soff[j] = o; o += g_cnt[j]; }
    }
    __syncthreads();
    int a0 = g_tpe[t * 2], a1 = g_tpe[t * 2 + 1];
    int e0 = a0 >> 16, e1 = a1 >> 16;
    int row0 = soff[e0] + (a0 & 0xFFFF);
    int row1 = soff[e1] + (a1 & 0xFFFF);
    float d0 = g_deqh[row0] * g_mval[10 + e0] * g_tg[t * 2];
    float d1 = g_deqh[row1] * g_mval[10 + e1] * g_tg[t * 2 + 1];
    size_t r0 = (size_t)row0 * DIMX;
    size_t r1 = (size_t)row1 * DIMX;
    int4 p00 = ((const int4*)(g_yp0 + r0))[i];
    int4 p01 = ((const int4*)(g_yp1 + r0))[i];
    int4 p10 = ((const int4*)(g_yp0 + r1))[i];
    int4 p11 = ((const int4*)(g_yp1 + r1))[i];
    float4 o;
    o.x = (float)(p00.x + p01.x) * d0 + (float)(p10.x + p11.x) * d1;
    o.y = (float)(p00.y + p01.y) * d0 + (float)(p10.y + p11.y) * d1;
    o.z = (float)(p00.z + p01.z) * d0 + (float)(p10.z + p11.z) * d1;
    o.w = (float)(p00.w + p01.w) * d0 + (float)(p10.w + p11.w) * d1;
    ((float4*)(out + (size_t)t * DIMX))[i] = o;
}

// ---------------- launch ----------------
extern "C" void kernel_launch(void* const* d_in, const int* in_sizes, int n_in,
                              void* d_out, int out_size) {
    const float* x   = (const float*)d_in[0];
    const float* eps = (const float*)d_in[1];
    const float* wr  = (const float*)d_in[2];
    const float* wn  = (const float*)d_in[3];
    const float* w1  = (const float*)d_in[4];
    const float* w2  = (const float*)d_in[5];
    float* out = (float*)d_out;

    cudaFuncSetAttribute(bit_gemm<1>, cudaFuncAttributeMaxDynamicSharedMemorySize, GSMEM);
    cudaFuncSetAttribute(bit_gemm<2>, cudaFuncAttributeMaxDynamicSharedMemorySize, GSMEM);

    stats_partial<<<dim3(64, 18), 256>>>(wr, wn, w1, w2);       // 1
    finalize<<<1, 256>>>(wr, wn);                               // 2
    mega<<<dim3(32768, 1, 2), 256>>>(w1, x, eps);               // 3
    bit_gemm<1><<<dim3(HIDX / BN, TTOK / BM, NEXP), 256, GSMEM>>>(w2);   // 4 <- profiled
    h_quant<<<2 * TTOK, 256>>>();                               // 5
    bit_gemm<2><<<dim3(DIMX / BN, TTOK / BM, NEXP * 2), 256, GSMEM>>>(nullptr);  // 6 (K-split)
    combine<<<TTOK, 256>>>(out);                                // 7
}